// round 8
// baseline (speedup 1.0000x reference)
#include <cuda_runtime.h>
#include <cstdint>

// QuantizedLinear: y[b,o] = scale[o] * sum_k x[b,k]*W[o,k] + bias[o]
//   x: float32 [16,4096], W: int32 [11008,4096] (int8-range values),
//   scale/bias: float32 [11008], out: float32 [16,11008]
//
// Strategy:
//   - DRAM-bound on the 180 MB int32 weight stream (floor ~22.5us @ 8TB/s).
//   - Use packed fma.rn.f32x2 (Blackwell) so fp32 compute (721M MACs) stays
//     under the memory floor.
//   - Pre-pack x into batch-pairs xp[8][4096] (float2) so ulonglong2 global
//     loads ARE the f32x2 operands (no packing MOVs on the hot path).
//   - 4 output channels per warp; lanes stride K with int4 weight loads
//     (__ldcs: weights are touched exactly once -> streaming, keep L1 for xp).
//   - K split into two sequential launches so each phase's xp working set
//     (128 KB) fits in L1 (228 KB); phase 2 accumulates onto out.

#define IN_F    4096
#define OUT_F   11008
#define BATCH   16
#define NPAIR   (BATCH / 2)     // 8 batch pairs
#define CH      4               // output channels per warp
#define THREADS 128

// Packed x: pair p, element k -> {x[2p][k], x[2p+1][k]}  (256 KB)
__device__ __align__(16) float g_xp[BATCH * IN_F];

__global__ void pack_x_kernel(const float* __restrict__ x) {
    int idx = blockIdx.x * blockDim.x + threadIdx.x;  // over 8*4096 pairs
    if (idx >= NPAIR * IN_F) return;
    int p = idx >> 12;            // / IN_F
    int k = idx & (IN_F - 1);
    float2 v;
    v.x = x[(2 * p)     * IN_F + k];
    v.y = x[(2 * p + 1) * IN_F + k];
    reinterpret_cast<float2*>(g_xp)[idx] = v;
}

__device__ __forceinline__ unsigned long long dup_f32(float a) {
    unsigned long long r;
    asm("mov.b64 %0, {%1, %1};" : "=l"(r) : "f"(a));
    return r;
}

__device__ __forceinline__ void fma2(unsigned long long& acc,
                                     unsigned long long a,
                                     unsigned long long b) {
    asm("fma.rn.f32x2 %0, %1, %2, %0;" : "+l"(acc) : "l"(a), "l"(b));
}

__global__ void __launch_bounds__(THREADS)
qlin_kernel(const int*   __restrict__ W,
            const float* __restrict__ scale,
            const float* __restrict__ bias,
            float*       __restrict__ out,
            int kv_base,      // starting int4-index within a weight row
            int k_iters,      // iterations of 32 int4 (=128 elements) each
            int add_prev)     // phase 2: accumulate onto out, skip bias
{
    const int lane = threadIdx.x & 31;
    const int gw   = (blockIdx.x * THREADS + threadIdx.x) >> 5;
    const int o0   = gw * CH;
    if (o0 >= OUT_F) return;    // never taken with exact grid; safety only

    // acc[c][p] is an f32x2 pair: {sum for batch 2p, sum for batch 2p+1}
    unsigned long long acc[CH][NPAIR];
#pragma unroll
    for (int c = 0; c < CH; ++c)
#pragma unroll
        for (int p = 0; p < NPAIR; ++p) acc[c][p] = 0ull;

    const int4*       Wv = reinterpret_cast<const int4*>(W);
    const ulonglong2* Xv = reinterpret_cast<const ulonglong2*>(g_xp);

    for (int it = 0; it < k_iters; ++it) {
        const int kv = kv_base + it * 32 + lane;   // int4 index in [0,1024)

        int4 wi[CH];
#pragma unroll
        for (int c = 0; c < CH; ++c)
            wi[c] = __ldcs(&Wv[(o0 + c) * (IN_F / 4) + kv]);  // streaming

        unsigned long long wp[CH][4];
#pragma unroll
        for (int c = 0; c < CH; ++c) {
            wp[c][0] = dup_f32((float)wi[c].x);
            wp[c][1] = dup_f32((float)wi[c].y);
            wp[c][2] = dup_f32((float)wi[c].z);
            wp[c][3] = dup_f32((float)wi[c].w);
        }

#pragma unroll
        for (int p = 0; p < NPAIR; ++p) {
            // xa = pairs for k,k+1 ; xb = pairs for k+2,k+3 (k = 4*kv)
            ulonglong2 xa = Xv[p * (IN_F / 2) + kv * 2];
            ulonglong2 xb = Xv[p * (IN_F / 2) + kv * 2 + 1];
#pragma unroll
            for (int c = 0; c < CH; ++c) {
                fma2(acc[c][p], wp[c][0], xa.x);
                fma2(acc[c][p], wp[c][1], xa.y);
                fma2(acc[c][p], wp[c][2], xb.x);
                fma2(acc[c][p], wp[c][3], xb.y);
            }
        }
    }

    // Epilogue: warp-reduce each (channel, batch) partial, write/accumulate.
#pragma unroll
    for (int c = 0; c < CH; ++c) {
        const int   o  = o0 + c;
        const float sc = scale[o];
        const float bi = bias[o];
#pragma unroll
        for (int p = 0; p < NPAIR; ++p) {
            float lo, hi;
            asm("mov.b64 {%0, %1}, %2;" : "=f"(lo), "=f"(hi) : "l"(acc[c][p]));
#pragma unroll
            for (int off = 16; off > 0; off >>= 1) {
                lo += __shfl_xor_sync(0xffffffffu, lo, off);
                hi += __shfl_xor_sync(0xffffffffu, hi, off);
            }
            if (lane == 0) {
                const int i0 = (2 * p)     * OUT_F + o;
                const int i1 = (2 * p + 1) * OUT_F + o;
                const float b0 = add_prev ? out[i0] : bi;
                const float b1 = add_prev ? out[i1] : bi;
                out[i0] = lo * sc + b0;
                out[i1] = hi * sc + b1;
            }
        }
    }
}

extern "C" void kernel_launch(void* const* d_in, const int* in_sizes, int n_in,
                              void* d_out, int out_size) {
    // metadata order: x (f32), weight_int8 (int32), weight_scale (f32), bias (f32)
    const float* x     = (const float*)d_in[0];
    const int*   W     = (const int*)d_in[1];
    const float* scale = (const float*)d_in[2];
    const float* bias  = (const float*)d_in[3];
    float*       out   = (float*)d_out;
    (void)in_sizes; (void)n_in; (void)out_size;

    pack_x_kernel<<<(NPAIR * IN_F + 255) / 256, 256>>>(x);

    const int warps  = OUT_F / CH;               // 2752
    const int blocks = warps * 32 / THREADS;     // 688 CTAs of 128 threads

    // Phase 1: K elements [0, 2048)   -> out = partial*scale + bias
    qlin_kernel<<<blocks, THREADS>>>(W, scale, bias, out,   0, 16, 0);
    // Phase 2: K elements [2048, 4096) -> out += partial*scale
    qlin_kernel<<<blocks, THREADS>>>(W, scale, bias, out, 512, 16, 1);
}

// round 9
// speedup vs baseline: 1.3133x; 1.3133x over previous
#include <cuda_runtime.h>
#include <cstdint>

// QuantizedLinear: y[b,o] = scale[o] * sum_k x[b,k]*W[o,k] + bias[o]
//   x: f32 [16,4096], W: int32 [11008,4096] (int8-range), scale/bias f32,
//   out f32 [16,11008].
//
// R8 redesign (fixing L1tex wavefront bound of R5):
//   - acc pairs by K-parity, not batch: acc[c][b] = f32x2 {sum even k, sum odd k}.
//     => x operand for fma.rn.f32x2 is the NATIVE x row layout (16B/lane,
//     contiguous), and weight pairs come straight from int4 conversion.
//     No pack kernel, no operand-duplication MOVs.
//   - x is staged in 32KB smem chunks (512 k each, 8 chunks) and read via
//     LDS.128 (conflict-free: 16B lane stride => each 8-lane phase hits all
//     32 banks once). x traffic (704MB) moves off the L1tex wavefront queue
//     onto the smem crossbar (128 B/cyc/SM).
//   - Weights stream once via __ldcs (evict-first), fully coalesced.
//   - Single kernel over full K (smem removes the L1-residency constraint),
//     so one launch, bias folded in, no out read-modify-write.

#define IN_F    4096
#define OUT_F   11008
#define BATCH   16
#define CH      4                       // output channels per warp
#define WARPS_PER_CTA 4
#define THREADS (WARPS_PER_CTA * 32)    // 128
#define KV_ROW  (IN_F / 4)              // 1024 int4 (or float4) per row
#define CHUNK_KV 128                    // float4 units per chunk = 512 floats
#define NCHUNK  (KV_ROW / CHUNK_KV)     // 8
#define ITERS_PER_CHUNK (CHUNK_KV / 32) // 4

__device__ __forceinline__ unsigned long long pack2(float lo, float hi) {
    unsigned long long r;
    asm("mov.b64 %0, {%1, %2};" : "=l"(r) : "f"(lo), "f"(hi));
    return r;
}

__device__ __forceinline__ void fma2(unsigned long long& acc,
                                     unsigned long long a,
                                     unsigned long long b) {
    asm("fma.rn.f32x2 %0, %1, %2, %0;" : "+l"(acc) : "l"(a), "l"(b));
}

__global__ void __launch_bounds__(THREADS, 2)
qlin_kernel(const float4* __restrict__ X,     // x viewed as [16][1024] float4
            const int4*   __restrict__ Wv,    // W viewed as [11008][1024] int4
            const float*  __restrict__ scale,
            const float*  __restrict__ bias,
            float*        __restrict__ out)
{
    __shared__ float4 xs[BATCH * CHUNK_KV];   // 32 KB: [b][kvl]

    const int tid  = threadIdx.x;
    const int lane = tid & 31;
    const int warp = tid >> 5;
    const int o0   = (blockIdx.x * WARPS_PER_CTA + warp) * CH;

    // acc[c][b]: f32x2 pair = {partial sum over even k, over odd k}
    unsigned long long acc[CH][BATCH];
#pragma unroll
    for (int c = 0; c < CH; ++c)
#pragma unroll
        for (int b = 0; b < BATCH; ++b) acc[c][b] = 0ull;

#pragma unroll 1
    for (int chunk = 0; chunk < NCHUNK; ++chunk) {
        __syncthreads();   // previous chunk's reads done before overwrite
        // Stage x chunk: 2048 float4 by 128 threads (16 each), coalesced.
#pragma unroll
        for (int i = 0; i < (BATCH * CHUNK_KV) / THREADS; ++i) {
            const int idx = i * THREADS + tid;        // = b*CHUNK_KV + kvl
            const int b   = idx / CHUNK_KV;
            const int kvl = idx % CHUNK_KV;
            xs[idx] = X[b * KV_ROW + chunk * CHUNK_KV + kvl];
        }
        __syncthreads();

#pragma unroll
        for (int it = 0; it < ITERS_PER_CHUNK; ++it) {
            const int kvl = it * 32 + lane;             // 0..127
            const int kv  = chunk * CHUNK_KV + kvl;     // 0..1023

            // 4 channels' weights for k = 4kv..4kv+3 (streaming, coalesced)
            int4 wi[CH];
#pragma unroll
            for (int c = 0; c < CH; ++c)
                wi[c] = __ldcs(&Wv[(o0 + c) * KV_ROW + kv]);

            // Natural k-pairs: {w[4kv],w[4kv+1]} and {w[4kv+2],w[4kv+3]}
            unsigned long long wp[CH][2];
#pragma unroll
            for (int c = 0; c < CH; ++c) {
                wp[c][0] = pack2((float)wi[c].x, (float)wi[c].y);
                wp[c][1] = pack2((float)wi[c].z, (float)wi[c].w);
            }

#pragma unroll
            for (int b = 0; b < BATCH; ++b) {
                // x[b][4kv..4kv+3]: 16B contiguous, conflict-free LDS.128
                const ulonglong2 xv = *reinterpret_cast<const ulonglong2*>(
                    &xs[b * CHUNK_KV + kvl]);
#pragma unroll
                for (int c = 0; c < CH; ++c) {
                    fma2(acc[c][b], wp[c][0], xv.x);
                    fma2(acc[c][b], wp[c][1], xv.y);
                }
            }
        }
    }

    // Epilogue: fold k-parity halves, warp-reduce over lanes (k-strided),
    // scale + bias, write.
#pragma unroll
    for (int c = 0; c < CH; ++c) {
        const int   o  = o0 + c;
        const float sc = scale[o];
        const float bi = bias[o];
#pragma unroll
        for (int b = 0; b < BATCH; ++b) {
            float lo, hi;
            asm("mov.b64 {%0, %1}, %2;" : "=f"(lo), "=f"(hi) : "l"(acc[c][b]));
            float s = lo + hi;
#pragma unroll
            for (int off = 16; off > 0; off >>= 1)
                s += __shfl_xor_sync(0xffffffffu, s, off);
            if (lane == 0) out[b * OUT_F + o] = s * sc + bi;
        }
    }
}

extern "C" void kernel_launch(void* const* d_in, const int* in_sizes, int n_in,
                              void* d_out, int out_size) {
    // metadata order: x (f32), weight_int8 (int32), weight_scale (f32), bias (f32)
    const float4* X     = (const float4*)d_in[0];
    const int4*   Wv    = (const int4*)d_in[1];
    const float*  scale = (const float*)d_in[2];
    const float*  bias  = (const float*)d_in[3];
    float*        out   = (float*)d_out;
    (void)in_sizes; (void)n_in; (void)out_size;

    const int blocks = OUT_F / (WARPS_PER_CTA * CH);   // 688
    qlin_kernel<<<blocks, THREADS>>>(X, Wv, scale, bias, out);
}